// round 12
// baseline (speedup 1.0000x reference)
#include <cuda_runtime.h>
#include <cuda_bf16.h>
#include <cstdint>
#include <cstddef>

// Problem dims (fixed)
#define TOK 8192
#define CDIM 1024
#define HDIM 4096

// GEMM1 tiling (128x128, 2 CTAs/SM)
#define BM 128
#define BN 128
#define BK 64
#define STAGES 3
#define STAGE_A (BM * BK * 2)              // 16 KB
#define STAGE_BYTES (2 * STAGE_A)          // 32 KB
#define SMEM_GEMM (STAGES * STAGE_BYTES)   // 96 KB -> 2 CTAs/SM

// GEMM2 tiling (128x64, 3 CTAs/SM)
#define B2M 128
#define B2N 64
#define STAGE2_A (B2M * BK * 2)            // 16 KB
#define STAGE2_B (B2N * BK * 2)            // 8 KB
#define STAGE2_BYTES (STAGE2_A + STAGE2_B) // 24 KB
#define SMEM_GEMM2 (STAGES * STAGE2_BYTES) // 72 KB -> 3 CTAs/SM

// ---------------------------------------------------------------------------
// Scratch (device globals; no allocations)
__device__ float          g_h[(size_t)TOK * HDIM];
__device__ __nv_bfloat16  g_xq[(size_t)TOK * CDIM];
__device__ __nv_bfloat16  g_hq[(size_t)TOK * HDIM];
__device__ __nv_bfloat16  g_wq1[(size_t)HDIM * CDIM];  // [N][K]
__device__ __nv_bfloat16  g_wq2[(size_t)CDIM * HDIM];  // [N][K]
__device__ float          g_dsw1[HDIM];
__device__ float          g_dsw2[CDIM];
__device__ unsigned       g_cmax1[HDIM];
__device__ unsigned       g_cmax2[CDIM];
__device__ unsigned       g_xmax_bits;
__device__ unsigned       g_hmax_bits;

__device__ __forceinline__ float clampq(float v) {
    return fminf(fmaxf(v, -127.f), 127.f);
}
__device__ __forceinline__ uint32_t smem_u32(const void* p) {
    uint32_t a;
    asm("{ .reg .u64 t; cvta.to.shared.u64 t, %1; cvt.u32.u64 %0, t; }"
        : "=r"(a) : "l"(p));
    return a;
}
__device__ __forceinline__ void ldgsts16(uint32_t s, const void* g) {
    asm volatile("cp.async.cg.shared.global [%0], [%1], 16;" :: "r"(s), "l"(g));
}
__device__ __forceinline__ void ldsm_x4(uint32_t& r0, uint32_t& r1,
                                        uint32_t& r2, uint32_t& r3, uint32_t a) {
    asm volatile("ldmatrix.sync.aligned.m8n8.x4.shared.b16 {%0,%1,%2,%3}, [%4];"
                 : "=r"(r0), "=r"(r1), "=r"(r2), "=r"(r3) : "r"(a));
}
__device__ __forceinline__ void mma16816(float* d, const uint32_t* a, const uint32_t* b) {
    asm volatile(
        "mma.sync.aligned.m16n8k16.row.col.f32.bf16.bf16.f32 "
        "{%0,%1,%2,%3}, {%4,%5,%6,%7}, {%8,%9}, {%0,%1,%2,%3};\n"
        : "+f"(d[0]), "+f"(d[1]), "+f"(d[2]), "+f"(d[3])
        : "r"(a[0]), "r"(a[1]), "r"(a[2]), "r"(a[3]), "r"(b[0]), "r"(b[1]));
}

// ---------------------------------------------------------------------------
__global__ void k_init() {
    int i = blockIdx.x * blockDim.x + threadIdx.x;
    if (i < HDIM) g_cmax1[i] = 0u;
    if (i < CDIM) g_cmax2[i] = 0u;
    if (i == 0) { g_xmax_bits = 0u; g_hmax_bits = 0u; }
}

// masked global |x| max
__global__ void k_absmax_x(const float4* __restrict__ x4,
                           const float* __restrict__ mask, int n4, int c4) {
    float lm = 0.f;
    for (int i = blockIdx.x * blockDim.x + threadIdx.x; i < n4;
         i += gridDim.x * blockDim.x) {
        float m = fabsf(mask[i / c4]);
        float4 v = x4[i];
        float a = fmaxf(fmaxf(fabsf(v.x), fabsf(v.y)), fmaxf(fabsf(v.z), fabsf(v.w)));
        lm = fmaxf(lm, a * m);
    }
    #pragma unroll
    for (int o = 16; o; o >>= 1) lm = fmaxf(lm, __shfl_xor_sync(0xffffffffu, lm, o));
    __shared__ float red[8];
    if ((threadIdx.x & 31) == 0) red[threadIdx.x >> 5] = lm;
    __syncthreads();
    if (threadIdx.x == 0) {
        float m = red[0];
        #pragma unroll
        for (int r = 1; r < 8; r++) m = fmaxf(m, red[r]);
        atomicMax(&g_xmax_bits, __float_as_uint(m));
    }
}

__global__ void k_quant_x(const float4* __restrict__ x4, int n4) {
    float sx = 127.f / fmaxf(__uint_as_float(g_xmax_bits), 1e-6f);
    for (int i = blockIdx.x * blockDim.x + threadIdx.x; i < n4;
         i += gridDim.x * blockDim.x) {
        float4 v = x4[i];
        __nv_bfloat16 t[4];
        t[0] = __float2bfloat16(clampq(rintf(v.x * sx)));
        t[1] = __float2bfloat16(clampq(rintf(v.y * sx)));
        t[2] = __float2bfloat16(clampq(rintf(v.z * sx)));
        t[3] = __float2bfloat16(clampq(rintf(v.w * sx)));
        reinterpret_cast<uint2*>(g_xq)[i] = *reinterpret_cast<uint2*>(t);
    }
}

__global__ void k_quant_h(int n4) {
    float sh = 127.f / fmaxf(__uint_as_float(g_hmax_bits), 1e-6f);
    const float4* h4 = reinterpret_cast<const float4*>(g_h);
    for (int i = blockIdx.x * blockDim.x + threadIdx.x; i < n4;
         i += gridDim.x * blockDim.x) {
        float4 v = __ldcs(h4 + i);
        __nv_bfloat16 t[4];
        t[0] = __float2bfloat16(clampq(rintf(v.x * sh)));
        t[1] = __float2bfloat16(clampq(rintf(v.y * sh)));
        t[2] = __float2bfloat16(clampq(rintf(v.z * sh)));
        t[3] = __float2bfloat16(clampq(rintf(v.w * sh)));
        __stcs(reinterpret_cast<uint2*>(g_hq) + i, *reinterpret_cast<uint2*>(t));
    }
}

// per-column |W| max; K split across blockIdx.y (16 rows each)
__global__ void k_wmax(const float* __restrict__ W, int which, int N) {
    unsigned* cmax = which ? g_cmax2 : g_cmax1;
    int n = blockIdx.x * blockDim.x + threadIdx.x;
    size_t k0 = (size_t)blockIdx.y * 16;
    float m0 = 0.f, m1 = 0.f, m2 = 0.f, m3 = 0.f;
    #pragma unroll
    for (int k = 0; k < 16; k += 4) {
        m0 = fmaxf(m0, fabsf(W[(k0 + k + 0) * N + n]));
        m1 = fmaxf(m1, fabsf(W[(k0 + k + 1) * N + n]));
        m2 = fmaxf(m2, fabsf(W[(k0 + k + 2) * N + n]));
        m3 = fmaxf(m3, fabsf(W[(k0 + k + 3) * N + n]));
    }
    atomicMax(&cmax[n], __float_as_uint(fmaxf(fmaxf(m0, m1), fmaxf(m2, m3))));
}

// quantize + transpose W[K,N] -> wq[N][K] bf16 (64k x 32n tile via smem)
__global__ void k_quant_wt(const float* __restrict__ W, int which, int K, int N) {
    __nv_bfloat16* wq = which ? g_wq2 : g_wq1;
    float* dsw = which ? g_dsw2 : g_dsw1;
    const unsigned* cmax = which ? g_cmax2 : g_cmax1;
    __shared__ float s[64 * 33];
    int t = threadIdx.x;
    int n0 = blockIdx.x * 32, k0 = blockIdx.y * 64;
    #pragma unroll
    for (int i = 0; i < 8; i++) {
        int idx = t + i * 256, r = idx >> 5, c = idx & 31;
        s[r * 33 + c] = W[(size_t)(k0 + r) * N + n0 + c];
    }
    __syncthreads();
    int nl = t >> 3, kl = (t & 7) * 8;
    float wmax = __uint_as_float(cmax[n0 + nl]);
    float sw = 127.f / fmaxf(wmax, 1e-6f);
    if (blockIdx.y == 0 && (t & 7) == 0) dsw[n0 + nl] = fmaxf(wmax, 1e-6f) / 127.f;
    __nv_bfloat16 tt[8];
    #pragma unroll
    for (int r = 0; r < 8; r++)
        tt[r] = __float2bfloat16(clampq(rintf(s[(kl + r) * 33 + nl] * sw)));
    *reinterpret_cast<uint4*>(wq + (size_t)(n0 + nl) * K + k0 + kl) =
        *reinterpret_cast<const uint4*>(tt);
}

// ---------------------------------------------------------------------------
// GEMM1: bf16 HMMA 128x128, 2 CTAs/SM, relu + fused masked h-max epilogue.
__global__ void __launch_bounds__(256, 2)
k_gemm1(const float* __restrict__ bias, const float* __restrict__ mask) {
    constexpr int N = HDIM, K = CDIM;
    const __nv_bfloat16* A = g_xq;
    const __nv_bfloat16* B = g_wq1;
    const float* dsw = g_dsw1;
    float* out = g_h;

    extern __shared__ __align__(128) char smem[];
    const uint32_t sb = smem_u32(smem);
    int t = threadIdx.x, lane = t & 31, w = t >> 5;
    int m0 = blockIdx.y * BM, n0 = blockIdx.x * BN;
    int wm = w & 3, wn = w >> 2;
    int mbase = wm * 32, nbase = wn * 64;

    float acc[2][8][4];
    #pragma unroll
    for (int a = 0; a < 2; a++)
        #pragma unroll
        for (int b = 0; b < 8; b++)
            #pragma unroll
            for (int c = 0; c < 4; c++) acc[a][b][c] = 0.f;

    auto load_tile = [&](int kt, int s) {
        const char* Ab = (const char*)A + ((size_t)m0 * K + (size_t)kt * BK) * 2;
        const char* Bb = (const char*)B + ((size_t)n0 * K + (size_t)kt * BK) * 2;
        uint32_t base = sb + s * STAGE_BYTES;
        #pragma unroll
        for (int i = 0; i < 4; i++) {
            int idx = t + i * 256;
            int row = idx >> 3, c = idx & 7;
            uint32_t d = (uint32_t)(row * 128 + ((c ^ (row & 7)) << 4));
            ldgsts16(base + d, Ab + (size_t)row * (K * 2) + c * 16);
            ldgsts16(base + STAGE_A + d, Bb + (size_t)row * (K * 2) + c * 16);
        }
    };

    int tile = lane >> 3, lrow = lane & 7;
    auto comp = [&](int s) {
        uint32_t uA = sb + s * STAGE_BYTES;
        uint32_t uB = uA + STAGE_A;
        #pragma unroll
        for (int ks = 0; ks < 4; ks++) {
            uint32_t af[2][4], bf[8][2];
            #pragma unroll
            for (int mt = 0; mt < 2; mt++) {
                int row = mbase + mt * 16 + ((tile & 1) << 3) + lrow;
                int ch = (ks * 2 + (tile >> 1)) ^ (row & 7);
                ldsm_x4(af[mt][0], af[mt][1], af[mt][2], af[mt][3],
                        uA + row * 128 + (ch << 4));
            }
            #pragma unroll
            for (int g = 0; g < 4; g++) {
                int row = nbase + g * 16 + ((tile >> 1) << 3) + lrow;
                int ch = (ks * 2 + (tile & 1)) ^ (row & 7);
                ldsm_x4(bf[2 * g][0], bf[2 * g][1], bf[2 * g + 1][0], bf[2 * g + 1][1],
                        uB + row * 128 + (ch << 4));
            }
            #pragma unroll
            for (int mt = 0; mt < 2; mt++)
                #pragma unroll
                for (int nt = 0; nt < 8; nt++)
                    mma16816(acc[mt][nt], af[mt], bf[nt]);
        }
    };

    load_tile(0, 0);
    asm volatile("cp.async.commit_group;" ::: "memory");
    load_tile(1, 1);
    asm volatile("cp.async.commit_group;" ::: "memory");

    const int niter = K / BK;
    for (int kt = 0; kt < niter; kt++) {
        asm volatile("cp.async.wait_group 1;" ::: "memory");
        __syncthreads();
        if (kt + 2 < niter) load_tile(kt + 2, (kt + 2) % STAGES);
        asm volatile("cp.async.commit_group;" ::: "memory");
        comp(kt % STAGES);
    }
    asm volatile("cp.async.wait_group 0;" ::: "memory");

    float dsA = fmaxf(__uint_as_float(g_xmax_bits), 1e-6f) / 127.f;
    float lmax = 0.f;
    #pragma unroll
    for (int mt = 0; mt < 2; mt++) {
        #pragma unroll
        for (int nt = 0; nt < 8; nt++) {
            int gcol = n0 + nbase + nt * 8 + (lane & 3) * 2;
            float ds0 = dsA * dsw[gcol], ds1 = dsA * dsw[gcol + 1];
            float bb0 = bias[gcol], bb1 = bias[gcol + 1];
            #pragma unroll
            for (int half = 0; half < 2; half++) {
                int grow = m0 + mbase + mt * 16 + (lane >> 2) + half * 8;
                float v0 = fmaxf(acc[mt][nt][half * 2 + 0] * ds0 + bb0, 0.f);
                float v1 = fmaxf(acc[mt][nt][half * 2 + 1] * ds1 + bb1, 0.f);
                lmax = fmaxf(lmax, fmaxf(v0, v1) * fabsf(mask[grow]));
                __stcs(reinterpret_cast<float2*>(&out[(size_t)grow * N + gcol]),
                       make_float2(v0, v1));
            }
        }
    }
    #pragma unroll
    for (int o = 16; o; o >>= 1)
        lmax = fmaxf(lmax, __shfl_xor_sync(0xffffffffu, lmax, o));
    __shared__ float red[8];
    if (lane == 0) red[w] = lmax;
    __syncthreads();
    if (t == 0) {
        float m = red[0];
        #pragma unroll
        for (int r = 1; r < 8; r++) m = fmaxf(m, red[r]);
        atomicMax(&g_hmax_bits, __float_as_uint(m));
    }
}

// ---------------------------------------------------------------------------
// GEMM2: bf16 HMMA 128x64, 3 CTAs/SM.
__global__ void __launch_bounds__(256, 3)
k_gemm2(const float* __restrict__ bias, float* __restrict__ outp) {
    constexpr int N = CDIM, K = HDIM;
    const __nv_bfloat16* A = g_hq;
    const __nv_bfloat16* B = g_wq2;
    const float* dsw = g_dsw2;

    extern __shared__ __align__(128) char smem[];
    const uint32_t sb = smem_u32(smem);
    int t = threadIdx.x, lane = t & 31, w = t >> 5;
    int m0 = blockIdx.y * B2M, n0 = blockIdx.x * B2N;
    int wm = w & 3, wn = w >> 2;
    int mbase = wm * 32, nbase = wn * 32;

    float acc[2][4][4];
    #pragma unroll
    for (int a = 0; a < 2; a++)
        #pragma unroll
        for (int b = 0; b < 4; b++)
            #pragma unroll
            for (int c = 0; c < 4; c++) acc[a][b][c] = 0.f;

    auto load_tile = [&](int kt, int s) {
        const char* Ab = (const char*)A + ((size_t)m0 * K + (size_t)kt * BK) * 2;
        const char* Bb = (const char*)B + ((size_t)n0 * K + (size_t)kt * BK) * 2;
        uint32_t base = sb + s * STAGE2_BYTES;
        #pragma unroll
        for (int i = 0; i < 4; i++) {
            int idx = t + i * 256;
            int row = idx >> 3, c = idx & 7;
            uint32_t d = (uint32_t)(row * 128 + ((c ^ (row & 7)) << 4));
            ldgsts16(base + d, Ab + (size_t)row * (K * 2) + c * 16);
        }
        #pragma unroll
        for (int i = 0; i < 2; i++) {
            int idx = t + i * 256;
            int row = idx >> 3, c = idx & 7;
            uint32_t d = (uint32_t)(row * 128 + ((c ^ (row & 7)) << 4));
            ldgsts16(base + STAGE2_A + d, Bb + (size_t)row * (K * 2) + c * 16);
        }
    };

    int tile = lane >> 3, lrow = lane & 7;
    auto comp = [&](int s) {
        uint32_t uA = sb + s * STAGE2_BYTES;
        uint32_t uB = uA + STAGE2_A;
        #pragma unroll
        for (int ks = 0; ks < 4; ks++) {
            uint32_t af[2][4], bf[4][2];
            #pragma unroll
            for (int mt = 0; mt < 2; mt++) {
                int row = mbase + mt * 16 + ((tile & 1) << 3) + lrow;
                int ch = (ks * 2 + (tile >> 1)) ^ (row & 7);
                ldsm_x4(af[mt][0], af[mt][1], af[mt][2], af[mt][3],
                        uA + row * 128 + (ch << 4));
            }
            #pragma unroll
            for (int g = 0; g < 2; g++) {
                int row = nbase + g * 16 + ((tile >> 1) << 3) + lrow;
                int ch = (ks * 2 + (tile & 1)) ^ (row & 7);
                ldsm_x4(bf[2 * g][0], bf[2 * g][1], bf[2 * g + 1][0], bf[2 * g + 1][1],
                        uB + row * 128 + (ch << 4));
            }
            #pragma unroll
            for (int mt = 0; mt < 2; mt++)
                #pragma unroll
                for (int nt = 0; nt < 4; nt++)
                    mma16816(acc[mt][nt], af[mt], bf[nt]);
        }
    };

    load_tile(0, 0);
    asm volatile("cp.async.commit_group;" ::: "memory");
    load_tile(1, 1);
    asm volatile("cp.async.commit_group;" ::: "memory");

    const int niter = K / BK;
    for (int kt = 0; kt < niter; kt++) {
        asm volatile("cp.async.wait_group 1;" ::: "memory");
        __syncthreads();
        if (kt + 2 < niter) load_tile(kt + 2, (kt + 2) % STAGES);
        asm volatile("cp.async.commit_group;" ::: "memory");
        comp(kt % STAGES);
    }
    asm volatile("cp.async.wait_group 0;" ::: "memory");

    float dsA = fmaxf(__uint_as_float(g_hmax_bits), 1e-6f) / 127.f;
    #pragma unroll
    for (int mt = 0; mt < 2; mt++) {
        #pragma unroll
        for (int nt = 0; nt < 4; nt++) {
            int gcol = n0 + nbase + nt * 8 + (lane & 3) * 2;
            float ds0 = dsA * dsw[gcol], ds1 = dsA * dsw[gcol + 1];
            float bb0 = bias[gcol], bb1 = bias[gcol + 1];
            #pragma unroll
            for (int half = 0; half < 2; half++) {
                int grow = m0 + mbase + mt * 16 + (lane >> 2) + half * 8;
                float v0 = acc[mt][nt][half * 2 + 0] * ds0 + bb0;
                float v1 = acc[mt][nt][half * 2 + 1] * ds1 + bb1;
                *reinterpret_cast<float2*>(&outp[(size_t)grow * N + gcol]) =
                    make_float2(v0, v1);
            }
        }
    }
}

// ---------------------------------------------------------------------------
extern "C" void kernel_launch(void* const* d_in, const int* in_sizes, int n_in,
                              void* d_out, int out_size) {
    const float* x    = (const float*)d_in[0];
    const float* mask = (const float*)d_in[1];
    const float* W1   = (const float*)d_in[2];
    const float* b1   = (const float*)d_in[3];
    const float* W2   = (const float*)d_in[4];
    const float* b2   = (const float*)d_in[5];
    float* out = (float*)d_out;

    // One-time infra (created on the first, uncaptured correctness call;
    // reused by every subsequent call — no device memory involved).
    static cudaStream_t s2 = nullptr;
    static cudaEvent_t ev0 = nullptr, evW1 = nullptr, evW2 = nullptr;
    if (!s2) {
        cudaStreamCreateWithFlags(&s2, cudaStreamNonBlocking);
        cudaEventCreateWithFlags(&ev0, cudaEventDisableTiming);
        cudaEventCreateWithFlags(&evW1, cudaEventDisableTiming);
        cudaEventCreateWithFlags(&evW2, cudaEventDisableTiming);
        cudaFuncSetAttribute(k_gemm1,
                             cudaFuncAttributeMaxDynamicSharedMemorySize, SMEM_GEMM);
        cudaFuncSetAttribute(k_gemm2,
                             cudaFuncAttributeMaxDynamicSharedMemorySize, SMEM_GEMM2);
    }
    cudaStream_t s0 = 0;  // harness capture stream (legacy default)

    // Main stream: init, then x-chain.
    k_init<<<16, 256, 0, s0>>>();
    cudaEventRecord(ev0, s0);

    // Side stream: weight quantization (W1 pre-GEMM1; W2 under GEMM1's shadow).
    cudaStreamWaitEvent(s2, ev0, 0);
    k_wmax<<<dim3(HDIM / 256, CDIM / 16), 256, 0, s2>>>(W1, 0, HDIM);
    k_quant_wt<<<dim3(HDIM / 32, CDIM / 64), 256, 0, s2>>>(W1, 0, CDIM, HDIM);
    cudaEventRecord(evW1, s2);
    k_wmax<<<dim3(CDIM / 256, HDIM / 16), 256, 0, s2>>>(W2, 1, CDIM);
    k_quant_wt<<<dim3(CDIM / 32, HDIM / 64), 256, 0, s2>>>(W2, 1, HDIM, CDIM);
    cudaEventRecord(evW2, s2);

    // Main stream continues concurrently with s2.
    k_absmax_x<<<1024, 256, 0, s0>>>((const float4*)x, mask,
                                     (TOK * CDIM) / 4, CDIM / 4);
    k_quant_x<<<1024, 256, 0, s0>>>((const float4*)x, (TOK * CDIM) / 4);

    cudaStreamWaitEvent(s0, evW1, 0);
    k_gemm1<<<dim3(HDIM / BN, TOK / BM), 256, SMEM_GEMM, s0>>>(b1, mask);

    k_quant_h<<<8192, 256, 0, s0>>>((TOK * HDIM) / 4);

    cudaStreamWaitEvent(s0, evW2, 0);
    k_gemm2<<<dim3(CDIM / B2N, TOK / B2M), 256, SMEM_GEMM2, s0>>>(b2, out);
}

// round 13
// speedup vs baseline: 1.4643x; 1.4643x over previous
#include <cuda_runtime.h>
#include <cuda_bf16.h>
#include <cstdint>
#include <cstddef>

// Problem dims (fixed)
#define TOK 8192
#define CDIM 1024
#define HDIM 4096

// GEMM1 tiling (128x128, 2 CTAs/SM)
#define BM 128
#define BN 128
#define BK 64
#define STAGES 3
#define STAGE_A (BM * BK * 2)              // 16 KB
#define STAGE_BYTES (2 * STAGE_A)          // 32 KB
#define SMEM_GEMM (STAGES * STAGE_BYTES)   // 96 KB -> 2 CTAs/SM

// GEMM2 tiling (128x64, 3 CTAs/SM)
#define B2M 128
#define B2N 64
#define STAGE2_A (B2M * BK * 2)            // 16 KB
#define STAGE2_B (B2N * BK * 2)            // 8 KB
#define STAGE2_BYTES (STAGE2_A + STAGE2_B) // 24 KB
#define SMEM_GEMM2 (STAGES * STAGE2_BYTES) // 72 KB -> 3 CTAs/SM

// ---------------------------------------------------------------------------
// Scratch (device globals; no allocations)
__device__ float          g_h[(size_t)TOK * HDIM];
__device__ __nv_bfloat16  g_xq[(size_t)TOK * CDIM];
__device__ __nv_bfloat16  g_hq[(size_t)TOK * HDIM];
__device__ __nv_bfloat16  g_wq1[(size_t)HDIM * CDIM];  // [N][K]
__device__ __nv_bfloat16  g_wq2[(size_t)CDIM * HDIM];  // [N][K]
__device__ float          g_dsw1[HDIM];
__device__ float          g_dsw2[CDIM];
__device__ unsigned       g_cmax1[HDIM];
__device__ unsigned       g_cmax2[CDIM];
__device__ unsigned       g_xmax_bits;
__device__ unsigned       g_hmax_bits;

__device__ __forceinline__ float clampq(float v) {
    return fminf(fmaxf(v, -127.f), 127.f);
}
__device__ __forceinline__ uint32_t smem_u32(const void* p) {
    uint32_t a;
    asm("{ .reg .u64 t; cvta.to.shared.u64 t, %1; cvt.u32.u64 %0, t; }"
        : "=r"(a) : "l"(p));
    return a;
}
__device__ __forceinline__ void ldgsts16(uint32_t s, const void* g) {
    asm volatile("cp.async.cg.shared.global [%0], [%1], 16;" :: "r"(s), "l"(g));
}
__device__ __forceinline__ void ldsm_x4(uint32_t& r0, uint32_t& r1,
                                        uint32_t& r2, uint32_t& r3, uint32_t a) {
    asm volatile("ldmatrix.sync.aligned.m8n8.x4.shared.b16 {%0,%1,%2,%3}, [%4];"
                 : "=r"(r0), "=r"(r1), "=r"(r2), "=r"(r3) : "r"(a));
}
__device__ __forceinline__ void mma16816(float* d, const uint32_t* a, const uint32_t* b) {
    asm volatile(
        "mma.sync.aligned.m16n8k16.row.col.f32.bf16.bf16.f32 "
        "{%0,%1,%2,%3}, {%4,%5,%6,%7}, {%8,%9}, {%0,%1,%2,%3};\n"
        : "+f"(d[0]), "+f"(d[1]), "+f"(d[2]), "+f"(d[3])
        : "r"(a[0]), "r"(a[1]), "r"(a[2]), "r"(a[3]), "r"(b[0]), "r"(b[1]));
}

// ---------------------------------------------------------------------------
__global__ void k_init() {
    int i = blockIdx.x * blockDim.x + threadIdx.x;
    if (i < HDIM) g_cmax1[i] = 0u;
    if (i < CDIM) g_cmax2[i] = 0u;
    if (i == 0) { g_xmax_bits = 0u; g_hmax_bits = 0u; }
}

// ---------------------------------------------------------------------------
// Combined stats pass: absmax_x (blocks 0..1023) || wmax1 (1024..2047)
// || wmax2 (2048..3071). Identical arithmetic to the split kernels.
__global__ void k_stats(const float4* __restrict__ x4,
                        const float* __restrict__ mask,
                        const float* __restrict__ W1,
                        const float* __restrict__ W2) {
    int b = blockIdx.x;
    int t = threadIdx.x;
    if (b < 1024) {
        // masked |x| max
        const int n4 = (TOK * CDIM) / 4, c4 = CDIM / 4;
        float lm = 0.f;
        for (int i = b * 256 + t; i < n4; i += 1024 * 256) {
            float m = fabsf(mask[i / c4]);
            float4 v = x4[i];
            float a = fmaxf(fmaxf(fabsf(v.x), fabsf(v.y)),
                            fmaxf(fabsf(v.z), fabsf(v.w)));
            lm = fmaxf(lm, a * m);
        }
        #pragma unroll
        for (int o = 16; o; o >>= 1)
            lm = fmaxf(lm, __shfl_xor_sync(0xffffffffu, lm, o));
        __shared__ float red[8];
        if ((t & 31) == 0) red[t >> 5] = lm;
        __syncthreads();
        if (t == 0) {
            float m = red[0];
            #pragma unroll
            for (int r = 1; r < 8; r++) m = fmaxf(m, red[r]);
            atomicMax(&g_xmax_bits, __float_as_uint(m));
        }
    } else {
        const float* W;
        unsigned* cmax;
        int N, bx, by;
        if (b < 2048) {
            int bb = b - 1024;                 // wmax1: 16 x 64
            W = W1; cmax = g_cmax1; N = HDIM;
            bx = bb % (HDIM / 256); by = bb / (HDIM / 256);
        } else {
            int bb = b - 2048;                 // wmax2: 4 x 256
            W = W2; cmax = g_cmax2; N = CDIM;
            bx = bb % (CDIM / 256); by = bb / (CDIM / 256);
        }
        int n = bx * 256 + t;
        size_t k0 = (size_t)by * 16;
        float m0 = 0.f, m1 = 0.f, m2 = 0.f, m3 = 0.f;
        #pragma unroll
        for (int k = 0; k < 16; k += 4) {
            m0 = fmaxf(m0, fabsf(W[(k0 + k + 0) * N + n]));
            m1 = fmaxf(m1, fabsf(W[(k0 + k + 1) * N + n]));
            m2 = fmaxf(m2, fabsf(W[(k0 + k + 2) * N + n]));
            m3 = fmaxf(m3, fabsf(W[(k0 + k + 3) * N + n]));
        }
        atomicMax(&cmax[n], __float_as_uint(fmaxf(fmaxf(m0, m1), fmaxf(m2, m3))));
    }
}

// ---------------------------------------------------------------------------
// Combined quantize pass: quant_x (blocks 0..1023) || quant_wt1 (1024..3071)
// || quant_wt2 (3072..5119). Identical arithmetic to the split kernels.
__global__ void k_quantall(const float4* __restrict__ x4,
                           const float* __restrict__ W1,
                           const float* __restrict__ W2) {
    __shared__ float s[64 * 33];
    int b = blockIdx.x;
    int t = threadIdx.x;
    if (b < 1024) {
        const int n4 = (TOK * CDIM) / 4;
        float sx = 127.f / fmaxf(__uint_as_float(g_xmax_bits), 1e-6f);
        for (int i = b * 256 + t; i < n4; i += 1024 * 256) {
            float4 v = x4[i];
            __nv_bfloat16 tq[4];
            tq[0] = __float2bfloat16(clampq(rintf(v.x * sx)));
            tq[1] = __float2bfloat16(clampq(rintf(v.y * sx)));
            tq[2] = __float2bfloat16(clampq(rintf(v.z * sx)));
            tq[3] = __float2bfloat16(clampq(rintf(v.w * sx)));
            reinterpret_cast<uint2*>(g_xq)[i] = *reinterpret_cast<uint2*>(tq);
        }
        return;
    }
    const float* W;
    __nv_bfloat16* wq;
    float* dsw;
    const unsigned* cmax;
    int K, N, bx, by;
    if (b < 3072) {
        int bb = b - 1024;                     // wt1: 128 x 16
        W = W1; wq = g_wq1; dsw = g_dsw1; cmax = g_cmax1;
        K = CDIM; N = HDIM;
        bx = bb % (HDIM / 32); by = bb / (HDIM / 32);
    } else {
        int bb = b - 3072;                     // wt2: 32 x 64
        W = W2; wq = g_wq2; dsw = g_dsw2; cmax = g_cmax2;
        K = HDIM; N = CDIM;
        bx = bb % (CDIM / 32); by = bb / (CDIM / 32);
    }
    int n0 = bx * 32, k0 = by * 64;
    #pragma unroll
    for (int i = 0; i < 8; i++) {
        int idx = t + i * 256, r = idx >> 5, c = idx & 31;
        s[r * 33 + c] = W[(size_t)(k0 + r) * N + n0 + c];
    }
    __syncthreads();
    int nl = t >> 3, kl = (t & 7) * 8;
    float wmax = __uint_as_float(cmax[n0 + nl]);
    float sw = 127.f / fmaxf(wmax, 1e-6f);
    if (by == 0 && (t & 7) == 0) dsw[n0 + nl] = fmaxf(wmax, 1e-6f) / 127.f;
    __nv_bfloat16 tt[8];
    #pragma unroll
    for (int r = 0; r < 8; r++)
        tt[r] = __float2bfloat16(clampq(rintf(s[(kl + r) * 33 + nl] * sw)));
    *reinterpret_cast<uint4*>(wq + (size_t)(n0 + nl) * K + k0 + kl) =
        *reinterpret_cast<const uint4*>(tt);
}

// ---------------------------------------------------------------------------
__global__ void k_quant_h(int n4) {
    float sh = 127.f / fmaxf(__uint_as_float(g_hmax_bits), 1e-6f);
    const float4* h4 = reinterpret_cast<const float4*>(g_h);
    for (int i = blockIdx.x * blockDim.x + threadIdx.x; i < n4;
         i += gridDim.x * blockDim.x) {
        float4 v = __ldcs(h4 + i);
        __nv_bfloat16 t[4];
        t[0] = __float2bfloat16(clampq(rintf(v.x * sh)));
        t[1] = __float2bfloat16(clampq(rintf(v.y * sh)));
        t[2] = __float2bfloat16(clampq(rintf(v.z * sh)));
        t[3] = __float2bfloat16(clampq(rintf(v.w * sh)));
        __stcs(reinterpret_cast<uint2*>(g_hq) + i, *reinterpret_cast<uint2*>(t));
    }
}

// ---------------------------------------------------------------------------
// GEMM1: bf16 HMMA 128x128, 2 CTAs/SM, relu + fused masked h-max epilogue.
__global__ void __launch_bounds__(256, 2)
k_gemm1(const float* __restrict__ bias, const float* __restrict__ mask) {
    constexpr int N = HDIM, K = CDIM;
    const __nv_bfloat16* A = g_xq;
    const __nv_bfloat16* B = g_wq1;
    const float* dsw = g_dsw1;
    float* out = g_h;

    extern __shared__ __align__(128) char smem[];
    const uint32_t sb = smem_u32(smem);
    int t = threadIdx.x, lane = t & 31, w = t >> 5;
    int m0 = blockIdx.y * BM, n0 = blockIdx.x * BN;
    int wm = w & 3, wn = w >> 2;
    int mbase = wm * 32, nbase = wn * 64;

    float acc[2][8][4];
    #pragma unroll
    for (int a = 0; a < 2; a++)
        #pragma unroll
        for (int b = 0; b < 8; b++)
            #pragma unroll
            for (int c = 0; c < 4; c++) acc[a][b][c] = 0.f;

    auto load_tile = [&](int kt, int s) {
        const char* Ab = (const char*)A + ((size_t)m0 * K + (size_t)kt * BK) * 2;
        const char* Bb = (const char*)B + ((size_t)n0 * K + (size_t)kt * BK) * 2;
        uint32_t base = sb + s * STAGE_BYTES;
        #pragma unroll
        for (int i = 0; i < 4; i++) {
            int idx = t + i * 256;
            int row = idx >> 3, c = idx & 7;
            uint32_t d = (uint32_t)(row * 128 + ((c ^ (row & 7)) << 4));
            ldgsts16(base + d, Ab + (size_t)row * (K * 2) + c * 16);
            ldgsts16(base + STAGE_A + d, Bb + (size_t)row * (K * 2) + c * 16);
        }
    };

    int tile = lane >> 3, lrow = lane & 7;
    auto comp = [&](int s) {
        uint32_t uA = sb + s * STAGE_BYTES;
        uint32_t uB = uA + STAGE_A;
        #pragma unroll
        for (int ks = 0; ks < 4; ks++) {
            uint32_t af[2][4], bf[8][2];
            #pragma unroll
            for (int mt = 0; mt < 2; mt++) {
                int row = mbase + mt * 16 + ((tile & 1) << 3) + lrow;
                int ch = (ks * 2 + (tile >> 1)) ^ (row & 7);
                ldsm_x4(af[mt][0], af[mt][1], af[mt][2], af[mt][3],
                        uA + row * 128 + (ch << 4));
            }
            #pragma unroll
            for (int g = 0; g < 4; g++) {
                int row = nbase + g * 16 + ((tile >> 1) << 3) + lrow;
                int ch = (ks * 2 + (tile & 1)) ^ (row & 7);
                ldsm_x4(bf[2 * g][0], bf[2 * g][1], bf[2 * g + 1][0], bf[2 * g + 1][1],
                        uB + row * 128 + (ch << 4));
            }
            #pragma unroll
            for (int mt = 0; mt < 2; mt++)
                #pragma unroll
                for (int nt = 0; nt < 8; nt++)
                    mma16816(acc[mt][nt], af[mt], bf[nt]);
        }
    };

    load_tile(0, 0);
    asm volatile("cp.async.commit_group;" ::: "memory");
    load_tile(1, 1);
    asm volatile("cp.async.commit_group;" ::: "memory");

    const int niter = K / BK;
    for (int kt = 0; kt < niter; kt++) {
        asm volatile("cp.async.wait_group 1;" ::: "memory");
        __syncthreads();
        if (kt + 2 < niter) load_tile(kt + 2, (kt + 2) % STAGES);
        asm volatile("cp.async.commit_group;" ::: "memory");
        comp(kt % STAGES);
    }
    asm volatile("cp.async.wait_group 0;" ::: "memory");

    float dsA = fmaxf(__uint_as_float(g_xmax_bits), 1e-6f) / 127.f;
    float lmax = 0.f;
    #pragma unroll
    for (int mt = 0; mt < 2; mt++) {
        #pragma unroll
        for (int nt = 0; nt < 8; nt++) {
            int gcol = n0 + nbase + nt * 8 + (lane & 3) * 2;
            float ds0 = dsA * dsw[gcol], ds1 = dsA * dsw[gcol + 1];
            float bb0 = bias[gcol], bb1 = bias[gcol + 1];
            #pragma unroll
            for (int half = 0; half < 2; half++) {
                int grow = m0 + mbase + mt * 16 + (lane >> 2) + half * 8;
                float v0 = fmaxf(acc[mt][nt][half * 2 + 0] * ds0 + bb0, 0.f);
                float v1 = fmaxf(acc[mt][nt][half * 2 + 1] * ds1 + bb1, 0.f);
                lmax = fmaxf(lmax, fmaxf(v0, v1) * fabsf(mask[grow]));
                __stcs(reinterpret_cast<float2*>(&out[(size_t)grow * N + gcol]),
                       make_float2(v0, v1));
            }
        }
    }
    #pragma unroll
    for (int o = 16; o; o >>= 1)
        lmax = fmaxf(lmax, __shfl_xor_sync(0xffffffffu, lmax, o));
    __shared__ float red[8];
    if (lane == 0) red[w] = lmax;
    __syncthreads();
    if (t == 0) {
        float m = red[0];
        #pragma unroll
        for (int r = 1; r < 8; r++) m = fmaxf(m, red[r]);
        atomicMax(&g_hmax_bits, __float_as_uint(m));
    }
}

// ---------------------------------------------------------------------------
// GEMM2: bf16 HMMA 128x64, 3 CTAs/SM.
__global__ void __launch_bounds__(256, 3)
k_gemm2(const float* __restrict__ bias, float* __restrict__ outp) {
    constexpr int N = CDIM, K = HDIM;
    const __nv_bfloat16* A = g_hq;
    const __nv_bfloat16* B = g_wq2;
    const float* dsw = g_dsw2;

    extern __shared__ __align__(128) char smem[];
    const uint32_t sb = smem_u32(smem);
    int t = threadIdx.x, lane = t & 31, w = t >> 5;
    int m0 = blockIdx.y * B2M, n0 = blockIdx.x * B2N;
    int wm = w & 3, wn = w >> 2;
    int mbase = wm * 32, nbase = wn * 32;

    float acc[2][4][4];
    #pragma unroll
    for (int a = 0; a < 2; a++)
        #pragma unroll
        for (int b = 0; b < 4; b++)
            #pragma unroll
            for (int c = 0; c < 4; c++) acc[a][b][c] = 0.f;

    auto load_tile = [&](int kt, int s) {
        const char* Ab = (const char*)A + ((size_t)m0 * K + (size_t)kt * BK) * 2;
        const char* Bb = (const char*)B + ((size_t)n0 * K + (size_t)kt * BK) * 2;
        uint32_t base = sb + s * STAGE2_BYTES;
        #pragma unroll
        for (int i = 0; i < 4; i++) {
            int idx = t + i * 256;
            int row = idx >> 3, c = idx & 7;
            uint32_t d = (uint32_t)(row * 128 + ((c ^ (row & 7)) << 4));
            ldgsts16(base + d, Ab + (size_t)row * (K * 2) + c * 16);
        }
        #pragma unroll
        for (int i = 0; i < 2; i++) {
            int idx = t + i * 256;
            int row = idx >> 3, c = idx & 7;
            uint32_t d = (uint32_t)(row * 128 + ((c ^ (row & 7)) << 4));
            ldgsts16(base + STAGE2_A + d, Bb + (size_t)row * (K * 2) + c * 16);
        }
    };

    int tile = lane >> 3, lrow = lane & 7;
    auto comp = [&](int s) {
        uint32_t uA = sb + s * STAGE2_BYTES;
        uint32_t uB = uA + STAGE2_A;
        #pragma unroll
        for (int ks = 0; ks < 4; ks++) {
            uint32_t af[2][4], bf[4][2];
            #pragma unroll
            for (int mt = 0; mt < 2; mt++) {
                int row = mbase + mt * 16 + ((tile & 1) << 3) + lrow;
                int ch = (ks * 2 + (tile >> 1)) ^ (row & 7);
                ldsm_x4(af[mt][0], af[mt][1], af[mt][2], af[mt][3],
                        uA + row * 128 + (ch << 4));
            }
            #pragma unroll
            for (int g = 0; g < 2; g++) {
                int row = nbase + g * 16 + ((tile >> 1) << 3) + lrow;
                int ch = (ks * 2 + (tile & 1)) ^ (row & 7);
                ldsm_x4(bf[2 * g][0], bf[2 * g][1], bf[2 * g + 1][0], bf[2 * g + 1][1],
                        uB + row * 128 + (ch << 4));
            }
            #pragma unroll
            for (int mt = 0; mt < 2; mt++)
                #pragma unroll
                for (int nt = 0; nt < 4; nt++)
                    mma16816(acc[mt][nt], af[mt], bf[nt]);
        }
    };

    load_tile(0, 0);
    asm volatile("cp.async.commit_group;" ::: "memory");
    load_tile(1, 1);
    asm volatile("cp.async.commit_group;" ::: "memory");

    const int niter = K / BK;
    for (int kt = 0; kt < niter; kt++) {
        asm volatile("cp.async.wait_group 1;" ::: "memory");
        __syncthreads();
        if (kt + 2 < niter) load_tile(kt + 2, (kt + 2) % STAGES);
        asm volatile("cp.async.commit_group;" ::: "memory");
        comp(kt % STAGES);
    }
    asm volatile("cp.async.wait_group 0;" ::: "memory");

    float dsA = fmaxf(__uint_as_float(g_hmax_bits), 1e-6f) / 127.f;
    #pragma unroll
    for (int mt = 0; mt < 2; mt++) {
        #pragma unroll
        for (int nt = 0; nt < 4; nt++) {
            int gcol = n0 + nbase + nt * 8 + (lane & 3) * 2;
            float ds0 = dsA * dsw[gcol], ds1 = dsA * dsw[gcol + 1];
            float bb0 = bias[gcol], bb1 = bias[gcol + 1];
            #pragma unroll
            for (int half = 0; half < 2; half++) {
                int grow = m0 + mbase + mt * 16 + (lane >> 2) + half * 8;
                float v0 = acc[mt][nt][half * 2 + 0] * ds0 + bb0;
                float v1 = acc[mt][nt][half * 2 + 1] * ds1 + bb1;
                *reinterpret_cast<float2*>(&outp[(size_t)grow * N + gcol]) =
                    make_float2(v0, v1);
            }
        }
    }
}

// ---------------------------------------------------------------------------
extern "C" void kernel_launch(void* const* d_in, const int* in_sizes, int n_in,
                              void* d_out, int out_size) {
    const float* x    = (const float*)d_in[0];
    const float* mask = (const float*)d_in[1];
    const float* W1   = (const float*)d_in[2];
    const float* b1   = (const float*)d_in[3];
    const float* W2   = (const float*)d_in[4];
    const float* b2   = (const float*)d_in[5];
    float* out = (float*)d_out;

    cudaFuncSetAttribute(k_gemm1,
                         cudaFuncAttributeMaxDynamicSharedMemorySize, SMEM_GEMM);
    cudaFuncSetAttribute(k_gemm2,
                         cudaFuncAttributeMaxDynamicSharedMemorySize, SMEM_GEMM2);

    k_init<<<16, 256>>>();
    k_stats<<<3072, 256>>>((const float4*)x, mask, W1, W2);
    k_quantall<<<5120, 256>>>((const float4*)x, W1, W2);

    k_gemm1<<<dim3(HDIM / BN, TOK / BM), 256, SMEM_GEMM>>>(b1, mask);

    k_quant_h<<<8192, 256>>>((TOK * HDIM) / 4);

    k_gemm2<<<dim3(CDIM / B2N, TOK / B2M), 256, SMEM_GEMM2>>>(b2, out);
}